// round 4
// baseline (speedup 1.0000x reference)
#include <cuda_runtime.h>
#include <cstdint>

#define OUTF 11008
#define INF  4096
#define BATCH 8
#define SPLITK 2
#define KCHUNK 1024                     // columns per smem chunk
#define CHUNKS ((INF / SPLITK) / KCHUNK)  // 2
#define ROWS_PER_WARP 8
#define WARPS 4
#define CTA_THREADS 128
#define ROWS_PER_CTA (ROWS_PER_WARP * WARPS)   // 32

// XOR swizzle on bits [6:4] of a byte offset into the x smem tile, chosen so
// that compute-side lane-divergent LDS.128 (lanes' cols differ by 4) and the
// fill-side STS.32 are (near-)conflict-free.
#define SWZ(a) ((a) ^ (((((a) >> 7) ^ ((a) >> 10)) & 7) << 4))

// Packed f32x2 ops (Blackwell sm_103a).
__device__ __forceinline__ float2 ffma2(float2 a, float2 b, float2 c) {
    float2 d;
    asm("{\n\t.reg .b64 A,B,C,D;\n\t"
        "mov.b64 A,{%2,%3};\n\tmov.b64 B,{%4,%5};\n\tmov.b64 C,{%6,%7};\n\t"
        "fma.rn.f32x2 D,A,B,C;\n\tmov.b64 {%0,%1},D;\n\t}"
        : "=f"(d.x), "=f"(d.y)
        : "f"(a.x), "f"(a.y), "f"(b.x), "f"(b.y), "f"(c.x), "f"(c.y));
    return d;
}
__device__ __forceinline__ float2 fadd2(float2 a, float2 b) {
    float2 d;
    asm("{\n\t.reg .b64 A,B,D;\n\t"
        "mov.b64 A,{%2,%3};\n\tmov.b64 B,{%4,%5};\n\t"
        "add.rn.f32x2 D,A,B;\n\tmov.b64 {%0,%1},D;\n\t}"
        : "=f"(d.x), "=f"(d.y) : "f"(a.x), "f"(a.y), "f"(b.x), "f"(b.y));
    return d;
}
__device__ __forceinline__ float2 fmul2(float2 a, float2 b) {
    float2 d;
    asm("{\n\t.reg .b64 A,B,D;\n\t"
        "mov.b64 A,{%2,%3};\n\tmov.b64 B,{%4,%5};\n\t"
        "mul.rn.f32x2 D,A,B;\n\tmov.b64 {%0,%1},D;\n\t}"
        : "=f"(d.x), "=f"(d.y) : "f"(a.x), "f"(a.y), "f"(b.x), "f"(b.y));
    return d;
}

__device__ __forceinline__ float4 ldx(const char* xs, int col, int half) {
    int off = (col << 5) + (half << 4);
    off = SWZ(off);
    return *(const float4*)(xs + off);
}

__global__ void zero_kernel(float* __restrict__ out, int n) {
    int i = blockIdx.x * blockDim.x + threadIdx.x;
    if (i < n) out[i] = 0.0f;
}

__global__ __launch_bounds__(CTA_THREADS, 4)
void qlin_kernel(const float* __restrict__ x,
                 const int*   __restrict__ packed,
                 const float* __restrict__ scales,
                 float*       __restrict__ out) {
    // x chunk in smem, [col][batch] layout (32B per column), SWZ-swizzled.
    __shared__ __align__(16) float xs_f[KCHUNK * BATCH];  // 32 KB
    char* xs = (char*)xs_f;

    const int tid  = threadIdx.x;
    const int lane = tid & 31;
    const int warp = tid >> 5;
    const int rowbase = blockIdx.x * ROWS_PER_CTA + warp * ROWS_PER_WARP;

    float2 acc[ROWS_PER_WARP][4];   // [row][batch-pair]
    #pragma unroll
    for (int i = 0; i < ROWS_PER_WARP; i++)
        #pragma unroll
        for (int p = 0; p < 4; p++) acc[i][p] = make_float2(0.f, 0.f);

    const float2 m8 = make_float2(-8388616.0f, -8388616.0f);  // -(2^23+8)

    for (int ch = 0; ch < CHUNKS; ch++) {
        const int kbase = blockIdx.y * (INF / SPLITK) + ch * KCHUNK;

        __syncthreads();
        // ── Fill: lane = (row r = lane&7, colgroup g = lane>>3). Each warp-op
        // reads 8 rows × 4 consecutive float4s (64B/row) and scatters STS.32.
        {
            const int r = lane & 7;
            const int g = lane >> 3;
            const float* xrow = x + (size_t)r * INF + kbase;
            #pragma unroll
            for (int p = 0; p < 16; p++) {
                const int c = ((p * WARPS + warp) * 4 + g) * 4;  // col of this float4
                float4 v = *(const float4*)(xrow + c);
                #pragma unroll
                for (int k = 0; k < 4; k++) {
                    int off = ((c + k) << 5) + (r << 2);
                    off = SWZ(off);
                    *(float*)(xs + off) = (&v.x)[k];
                }
            }
        }
        __syncthreads();

        // ── Compute: lane owns int2 #(32t + lane) of the chunk's 256 int2s,
        // i.e. cols [128t + 4*lane, +4). Coalesced W LDG.64 (8B lane stride).
        const int*   pbase = packed + (size_t)rowbase * (INF / 2) + (kbase >> 1) + 2 * lane;
        const float* sbase = scales + (size_t)rowbase * (INF / 32) + (kbase >> 5) + (lane >> 3);

        #pragma unroll 2
        for (int t = 0; t < 8; t++) {
            int2  w2[ROWS_PER_WARP];
            float s [ROWS_PER_WARP];
            #pragma unroll
            for (int i = 0; i < ROWS_PER_WARP; i++)
                w2[i] = *(const int2*)(pbase + (size_t)i * (INF / 2) + 64 * t);
            #pragma unroll
            for (int i = 0; i < ROWS_PER_WARP; i++)
                s[i] = sbase[i * (INF / 32) + 4 * t];

            #pragma unroll
            for (int e = 0; e < 2; e++) {
                const int c0 = 128 * t + 4 * lane + 2 * e;   // cols c0, c0+1
                float4 xa0 = ldx(xs, c0,     0);  // col c0, batches 0-3
                float4 xb0 = ldx(xs, c0,     1);  // col c0, batches 4-7
                float4 xa1 = ldx(xs, c0 + 1, 0);
                float4 xb1 = ldx(xs, c0 + 1, 1);

                #pragma unroll
                for (int i = 0; i < ROWS_PER_WARP; i++) {
                    const int v = (e == 0) ? w2[i].x : w2[i].y;  // byte value 0..255
                    // magic-mantissa: float(0x4B000000|n) = 2^23+n exactly;
                    // (2^23+n)-(2^23+8) = n-8 exactly (Sterbenz); one rounding in mul.
                    const int lob = (v & 15) | 0x4B000000;
                    const int hib = ((v >> 4) & 15) | 0x4B000000;
                    float2 q  = fadd2(make_float2(__int_as_float(lob), __int_as_float(hib)), m8);
                    float2 wv = fmul2(q, make_float2(s[i], s[i]));  // (w_c0, w_c1)

                    float2 wl = make_float2(wv.x, wv.x);
                    float2 wh = make_float2(wv.y, wv.y);
                    acc[i][0] = ffma2(wl, make_float2(xa0.x, xa0.y), acc[i][0]);
                    acc[i][1] = ffma2(wl, make_float2(xa0.z, xa0.w), acc[i][1]);
                    acc[i][2] = ffma2(wl, make_float2(xb0.x, xb0.y), acc[i][2]);
                    acc[i][3] = ffma2(wl, make_float2(xb0.z, xb0.w), acc[i][3]);
                    acc[i][0] = ffma2(wh, make_float2(xa1.x, xa1.y), acc[i][0]);
                    acc[i][1] = ffma2(wh, make_float2(xa1.z, xa1.w), acc[i][1]);
                    acc[i][2] = ffma2(wh, make_float2(xb1.x, xb1.y), acc[i][2]);
                    acc[i][3] = ffma2(wh, make_float2(xb1.z, xb1.w), acc[i][3]);
                }
            }
        }
    }

    // ── Cross-lane reduction (lanes cover disjoint K columns).
    #pragma unroll
    for (int i = 0; i < ROWS_PER_WARP; i++) {
        #pragma unroll
        for (int p = 0; p < 4; p++) {
            float2 v = acc[i][p];
            #pragma unroll
            for (int m = 16; m > 0; m >>= 1) {
                v.x += __shfl_xor_sync(0xFFFFFFFF, v.x, m);
                v.y += __shfl_xor_sync(0xFFFFFFFF, v.y, m);
            }
            acc[i][p] = v;
        }
    }
    if (lane == 0) {
        #pragma unroll
        for (int i = 0; i < ROWS_PER_WARP; i++) {
            const int row = rowbase + i;
            #pragma unroll
            for (int p = 0; p < 4; p++) {
                atomicAdd(&out[(size_t)(2 * p)     * OUTF + row], acc[i][p].x);
                atomicAdd(&out[(size_t)(2 * p + 1) * OUTF + row], acc[i][p].y);
            }
        }
    }
}

extern "C" void kernel_launch(void* const* d_in, const int* in_sizes, int n_in,
                              void* d_out, int out_size) {
    const float* x      = (const float*)d_in[0];
    const int*   packed = (const int*)d_in[1];
    const float* scales = (const float*)d_in[2];
    float*       out    = (float*)d_out;

    zero_kernel<<<(out_size + 255) / 256, 256>>>(out, out_size);

    dim3 grid(OUTF / ROWS_PER_CTA, SPLITK);   // (344, 2)
    qlin_kernel<<<grid, CTA_THREADS>>>(x, packed, scales, out);
}